// round 2
// baseline (speedup 1.0000x reference)
#include <cuda_runtime.h>

#define NN 50000
#define D  64
#define NE 800000
#define H  128

// Scratch: h = (1+eps)*x + segment_sum(x[col], row). 16B-aligned for float4 /
// vector-red access. Static device array (no allocs allowed).
__device__ __align__(16) float g_h[NN * D];

// Flag: 1 if edge_index buffer is int64, 0 if int32. Set by detect_kernel.
__device__ int g_idx_is64;

// ---------------------------------------------------------------------------
// Kernel 0: detect edge_index dtype. Values are in [0, 50000). If the buffer
// is int32, reading it as int64 packs two indices -> value >= 2^32 unless the
// high word is zero (prob ~(1/50000)^128 across 128 samples => negligible).
// Deterministic for fixed input, graph-capturable.
// ---------------------------------------------------------------------------
__global__ void detect_kernel(const void* ei) {
    const long long* p = (const long long*)ei;
    int ok = 1;
    for (int i = 0; i < 64; i++) {
        long long v = p[i];
        if (v < 0 || v >= NN) ok = 0;
    }
    for (int i = 0; i < 64; i++) {
        long long v = p[NE + i];   // sample the col half too (if int64 layout)
        if (v < 0 || v >= NN) ok = 0;
    }
    g_idx_is64 = ok;
}

// ---------------------------------------------------------------------------
// Kernel 1: g_h = (1+eps) * x     (vectorized float4)
// ---------------------------------------------------------------------------
__global__ void init_h_kernel(const float* __restrict__ x,
                              const float* __restrict__ eps) {
    int i = blockIdx.x * blockDim.x + threadIdx.x;
    if (i < NN * D / 4) {
        float s = 1.0f + eps[0];
        float4 v = reinterpret_cast<const float4*>(x)[i];
        v.x *= s; v.y *= s; v.z *= s; v.w *= s;
        reinterpret_cast<float4*>(g_h)[i] = v;
    }
}

// ---------------------------------------------------------------------------
// Kernel 2: scatter-add. 16 consecutive threads handle one edge (256B row),
// so the gather and the reduction are contiguous/coalesced. The uniform
// branch on g_idx_is64 selects int64 vs int32 index reads.
// red.global.add.v4.f32 (sm_90+) cuts the atomic op count 4x vs scalar.
// ---------------------------------------------------------------------------
__global__ void scatter_kernel(const float* __restrict__ x,
                               const void* __restrict__ ei) {
    int idx = blockIdx.x * blockDim.x + threadIdx.x;   // up to 12.8M < 2^31
    if (idx >= NE * 16) return;
    int e = idx >> 4;
    int c = idx & 15;
    int dst_n, src_n;
    if (g_idx_is64) {
        const long long* p = (const long long*)ei;
        dst_n = (int)p[e];        // row (destination segment)
        src_n = (int)p[NE + e];   // col (gathered neighbor)
    } else {
        const int* p = (const int*)ei;
        dst_n = p[e];
        src_n = p[NE + e];
    }
    float4 v = reinterpret_cast<const float4*>(x + (size_t)src_n * D)[c];
    float* dst = g_h + (size_t)dst_n * D + c * 4;
    asm volatile("red.global.add.v4.f32 [%0], {%1, %2, %3, %4};"
                 :: "l"(dst), "f"(v.x), "f"(v.y), "f"(v.z), "f"(v.w)
                 : "memory");
}

// ---------------------------------------------------------------------------
// Kernel 3: fused 2-layer MLP. One thread per node. W1, W2, b1, b2 staged in
// shared memory (warp-uniform broadcast LDS.128). The 128-wide layer-1
// intermediate never leaves registers: each 4-wide chunk is ReLU'd and
// immediately folded into the 64-wide layer-2 accumulator.
// ---------------------------------------------------------------------------
__global__ __launch_bounds__(128)
void mlp_kernel(const float* __restrict__ W1, const float* __restrict__ b1,
                const float* __restrict__ W2, const float* __restrict__ b2,
                float* __restrict__ out) {
    extern __shared__ float smem[];
    float* sW1 = smem;              // 64*128 = 8192 floats
    float* sW2 = smem + 8192;       // 128*64 = 8192 floats
    float* sb1 = smem + 16384;      // 128
    float* sb2 = smem + 16512;      // 64
    int tid = threadIdx.x;

    for (int i = tid; i < 2048; i += 128)
        reinterpret_cast<float4*>(sW1)[i] = reinterpret_cast<const float4*>(W1)[i];
    for (int i = tid; i < 2048; i += 128)
        reinterpret_cast<float4*>(sW2)[i] = reinterpret_cast<const float4*>(W2)[i];
    if (tid < 128) sb1[tid] = b1[tid];
    if (tid < 64)  sb2[tid] = b2[tid];
    __syncthreads();

    int node = blockIdx.x * 128 + tid;
    if (node >= NN) return;

    // Load this node's h row (256B contiguous per thread)
    float h[D];
    const float4* hv = reinterpret_cast<const float4*>(g_h + (size_t)node * D);
#pragma unroll
    for (int k = 0; k < 16; k++) {
        float4 v = hv[k];
        h[4*k+0] = v.x; h[4*k+1] = v.y; h[4*k+2] = v.z; h[4*k+3] = v.w;
    }

    // Layer-2 accumulator initialized with b2
    float4 acc[16];
#pragma unroll
    for (int o = 0; o < 16; o++) acc[o] = reinterpret_cast<const float4*>(sb2)[o];

    // Loop over layer-1 outputs in chunks of 4
    for (int j4 = 0; j4 < 32; j4++) {
        float4 a = reinterpret_cast<const float4*>(sb1)[j4];
#pragma unroll
        for (int k = 0; k < D; k++) {
            float4 w = reinterpret_cast<const float4*>(sW1 + k * H)[j4];
            a.x = fmaf(h[k], w.x, a.x);
            a.y = fmaf(h[k], w.y, a.y);
            a.z = fmaf(h[k], w.z, a.z);
            a.w = fmaf(h[k], w.w, a.w);
        }
        float av[4] = { fmaxf(a.x, 0.f), fmaxf(a.y, 0.f),
                        fmaxf(a.z, 0.f), fmaxf(a.w, 0.f) };
#pragma unroll
        for (int jj = 0; jj < 4; jj++) {
            const float4* w2 = reinterpret_cast<const float4*>(sW2 + (j4*4 + jj) * D);
            float hj = av[jj];
#pragma unroll
            for (int o = 0; o < 16; o++) {
                float4 w = w2[o];
                acc[o].x = fmaf(hj, w.x, acc[o].x);
                acc[o].y = fmaf(hj, w.y, acc[o].y);
                acc[o].z = fmaf(hj, w.z, acc[o].z);
                acc[o].w = fmaf(hj, w.w, acc[o].w);
            }
        }
    }

    float4* orow = reinterpret_cast<float4*>(out + (size_t)node * D);
#pragma unroll
    for (int o = 0; o < 16; o++) orow[o] = acc[o];
}

// ---------------------------------------------------------------------------
extern "C" void kernel_launch(void* const* d_in, const int* in_sizes, int n_in,
                              void* d_out, int out_size) {
    const float* x   = (const float*)d_in[0];
    const void*  ei  = d_in[1];
    const float* W1  = (const float*)d_in[2];
    const float* b1  = (const float*)d_in[3];
    const float* W2  = (const float*)d_in[4];
    const float* b2  = (const float*)d_in[5];
    const float* eps = (const float*)d_in[6];
    float* out = (float*)d_out;

    detect_kernel<<<1, 1>>>(ei);
    init_h_kernel<<<(NN * D / 4 + 255) / 256, 256>>>(x, eps);
    scatter_kernel<<<(NE * 16 + 255) / 256, 256>>>(x, ei);

    const int SMEM = (8192 + 8192 + 128 + 64) * (int)sizeof(float);  // 66304 B
    cudaFuncSetAttribute(mlp_kernel, cudaFuncAttributeMaxDynamicSharedMemorySize, SMEM);
    mlp_kernel<<<(NN + 127) / 128, 128, SMEM>>>(W1, b1, W2, b2, out);
}

// round 3
// speedup vs baseline: 1.1531x; 1.1531x over previous
#include <cuda_runtime.h>

#define NN 50000
#define D  64
#define NE 800000
#define H  128

// Scratch buffers (static — no allocs allowed).
__device__ __align__(16) float g_h [NN * D];   // (1+eps)*x + scatter-sum
__device__ __align__(16) float g_h1[NN * H];   // relu(h@W1+b1)
__device__ int g_idx_is64;

// ---------------------------------------------------------------------------
// Kernel 0: detect edge_index dtype. Reads only the first 1KB (safe for both
// int32 and int64 layouts). Values are node ids in [0, NN): if the buffer is
// int32, an int64 read packs two ids -> >= 2^32 unless hi word is 0
// (P(miss) ~ (1/NN)^128, negligible).
// ---------------------------------------------------------------------------
__global__ void detect_kernel(const void* ei) {
    __shared__ int bad;
    if (threadIdx.x == 0) bad = 0;
    __syncthreads();
    const long long* p = (const long long*)ei;
    long long v = p[threadIdx.x];
    if (v < 0 || v >= NN) atomicOr(&bad, 1);
    __syncthreads();
    if (threadIdx.x == 0) g_idx_is64 = !bad;
}

// ---------------------------------------------------------------------------
// Kernel 1: g_h = (1+eps) * x
// ---------------------------------------------------------------------------
__global__ void init_h_kernel(const float* __restrict__ x,
                              const float* __restrict__ eps) {
    int i = blockIdx.x * blockDim.x + threadIdx.x;
    if (i < NN * D / 4) {
        float s = 1.0f + eps[0];
        float4 v = reinterpret_cast<const float4*>(x)[i];
        v.x *= s; v.y *= s; v.z *= s; v.w *= s;
        reinterpret_cast<float4*>(g_h)[i] = v;
    }
}

// ---------------------------------------------------------------------------
// Kernel 2: scatter-add, 16 threads per edge (contiguous 256B row),
// red.global.add.v4.f32 to quarter the atomic op count. Near LTS floor.
// ---------------------------------------------------------------------------
__global__ void scatter_kernel(const float* __restrict__ x,
                               const void* __restrict__ ei) {
    int idx = blockIdx.x * blockDim.x + threadIdx.x;
    if (idx >= NE * 16) return;
    int e = idx >> 4;
    int c = idx & 15;
    int dst_n, src_n;
    if (g_idx_is64) {
        const long long* p = (const long long*)ei;
        dst_n = (int)p[e];
        src_n = (int)p[NE + e];
    } else {
        const int* p = (const int*)ei;
        dst_n = p[e];
        src_n = p[NE + e];
    }
    float4 v = reinterpret_cast<const float4*>(x + (size_t)src_n * D)[c];
    float* dst = g_h + (size_t)dst_n * D + c * 4;
    asm volatile("red.global.add.v4.f32 [%0], {%1, %2, %3, %4};"
                 :: "l"(dst), "f"(v.x), "f"(v.y), "f"(v.z), "f"(v.w)
                 : "memory");
}

// ---------------------------------------------------------------------------
__device__ __forceinline__ void fma4(float4& c, float s, const float4& b) {
    c.x = fmaf(s, b.x, c.x); c.y = fmaf(s, b.y, c.y);
    c.z = fmaf(s, b.z, c.z); c.w = fmaf(s, b.w, c.w);
}

// ---------------------------------------------------------------------------
// Kernel 3: g_h1 = relu(g_h @ W1 + b1).  Tile: 128 nodes x 128 cols, K=64.
// 256 threads, 8x8 micro-tile. A staged k-major (transposed) in smem so the
// warp's A-frag loads are contiguous 256B (2 wavefronts); B-frag loads are
// broadcast. FMA-pipe-bound by design.
// ---------------------------------------------------------------------------
__global__ __launch_bounds__(256, 2)
void gemm1_kernel(const float* __restrict__ W1, const float* __restrict__ b1) {
    extern __shared__ float sm[];
    float* At = sm;            // [64][128]  (k-major h tile)
    float* sW = sm + 8192;     // [64][128]  (W1 as-is, k-major)
    float* sb = sm + 16384;    // [128]
    int tid = threadIdx.x;
    int tx = tid & 15, ty = tid >> 4;
    int r0 = blockIdx.x * 128;

    for (int i = tid; i < 2048; i += 256)
        ((float4*)sW)[i] = ((const float4*)W1)[i];
    if (tid < 128) sb[tid] = b1[tid];
    // Transposed stage of h tile: lanes walk rows (conflict-free STS).
    for (int f = tid; f < 2048; f += 256) {
        int row = f & 127, c4 = f >> 7;
        int gr = r0 + row; if (gr >= NN) gr = NN - 1;
        float4 v = ((const float4*)g_h)[gr * 16 + c4];
        float* d = At + (c4 * 4) * 128 + row;
        d[0] = v.x; d[128] = v.y; d[256] = v.z; d[384] = v.w;
    }
    __syncthreads();

    float4 bb0 = ((const float4*)sb)[ty];
    float4 bb1 = ((const float4*)sb)[ty + 16];
    float4 acc[2][4][2];
#pragma unroll
    for (int i = 0; i < 2; i++)
#pragma unroll
        for (int ni = 0; ni < 4; ni++) { acc[i][ni][0] = bb0; acc[i][ni][1] = bb1; }

#pragma unroll 8
    for (int k = 0; k < 64; k++) {
        const float4* Ar = (const float4*)(At + k * 128);
        const float4* Br = (const float4*)(sW + k * 128);
        float4 a0 = Ar[tx], a1 = Ar[tx + 16];
        float4 b0 = Br[ty], b1v = Br[ty + 16];
        float av0[4] = {a0.x, a0.y, a0.z, a0.w};
        float av1[4] = {a1.x, a1.y, a1.z, a1.w};
#pragma unroll
        for (int ni = 0; ni < 4; ni++) {
            fma4(acc[0][ni][0], av0[ni], b0);
            fma4(acc[0][ni][1], av0[ni], b1v);
            fma4(acc[1][ni][0], av1[ni], b0);
            fma4(acc[1][ni][1], av1[ni], b1v);
        }
    }

#pragma unroll
    for (int i = 0; i < 2; i++)
#pragma unroll
        for (int ni = 0; ni < 4; ni++) {
            int node = r0 + i * 64 + 4 * tx + ni;
            if (node < NN) {
                float4 v0 = acc[i][ni][0], v1 = acc[i][ni][1];
                v0.x = fmaxf(v0.x, 0.f); v0.y = fmaxf(v0.y, 0.f);
                v0.z = fmaxf(v0.z, 0.f); v0.w = fmaxf(v0.w, 0.f);
                v1.x = fmaxf(v1.x, 0.f); v1.y = fmaxf(v1.y, 0.f);
                v1.z = fmaxf(v1.z, 0.f); v1.w = fmaxf(v1.w, 0.f);
                float4* orow = (float4*)(g_h1 + (size_t)node * H);
                orow[ty]      = v0;
                orow[ty + 16] = v1;
            }
        }
}

// ---------------------------------------------------------------------------
// Kernel 4: out = g_h1 @ W2 + b2.  Tile: 128 nodes x 64 cols, K=128 streamed
// in two 64-chunks. 128 threads, 8x8 micro-tile. 49KB smem -> 4 blocks/SM.
// ---------------------------------------------------------------------------
__global__ __launch_bounds__(128, 4)
void gemm2_kernel(const float* __restrict__ W2, const float* __restrict__ b2,
                  float* __restrict__ out) {
    extern __shared__ float sm[];
    float* At = sm;            // [64][128]  (k-major h1 chunk)
    float* sW = sm + 8192;     // [64][64]   (W2 chunk, k-major)
    int tid = threadIdx.x;
    int tx = tid & 15, ty = tid >> 4;   // ty in 0..7
    int r0 = blockIdx.x * 128;

    float4 bb0 = ((const float4*)b2)[ty];
    float4 bb1 = ((const float4*)b2)[ty + 8];
    float4 acc[2][4][2];
#pragma unroll
    for (int i = 0; i < 2; i++)
#pragma unroll
        for (int ni = 0; ni < 4; ni++) { acc[i][ni][0] = bb0; acc[i][ni][1] = bb1; }

    for (int kc = 0; kc < 2; kc++) {
        for (int f = tid; f < 2048; f += 128) {
            int row = f & 127, c4 = f >> 7;      // c4 in 0..15
            int gr = r0 + row; if (gr >= NN) gr = NN - 1;
            float4 v = ((const float4*)g_h1)[gr * 32 + kc * 16 + c4];
            float* d = At + (c4 * 4) * 128 + row;
            d[0] = v.x; d[128] = v.y; d[256] = v.z; d[384] = v.w;
        }
        for (int i = tid; i < 1024; i += 128)
            ((float4*)sW)[i] = ((const float4*)W2)[kc * 1024 + i];
        __syncthreads();

#pragma unroll 8
        for (int k = 0; k < 64; k++) {
            const float4* Ar = (const float4*)(At + k * 128);
            const float4* Br = (const float4*)(sW + k * 64);
            float4 a0 = Ar[tx], a1 = Ar[tx + 16];
            float4 b0 = Br[ty], b1v = Br[ty + 8];
            float av0[4] = {a0.x, a0.y, a0.z, a0.w};
            float av1[4] = {a1.x, a1.y, a1.z, a1.w};
#pragma unroll
            for (int ni = 0; ni < 4; ni++) {
                fma4(acc[0][ni][0], av0[ni], b0);
                fma4(acc[0][ni][1], av0[ni], b1v);
                fma4(acc[1][ni][0], av1[ni], b0);
                fma4(acc[1][ni][1], av1[ni], b1v);
            }
        }
        __syncthreads();
    }

#pragma unroll
    for (int i = 0; i < 2; i++)
#pragma unroll
        for (int ni = 0; ni < 4; ni++) {
            int node = r0 + i * 64 + 4 * tx + ni;
            if (node < NN) {
                float4* orow = (float4*)(out + (size_t)node * D);
                orow[ty]     = acc[i][ni][0];
                orow[ty + 8] = acc[i][ni][1];
            }
        }
}

// ---------------------------------------------------------------------------
extern "C" void kernel_launch(void* const* d_in, const int* in_sizes, int n_in,
                              void* d_out, int out_size) {
    const float* x   = (const float*)d_in[0];
    const void*  ei  = d_in[1];
    const float* W1  = (const float*)d_in[2];
    const float* b1  = (const float*)d_in[3];
    const float* W2  = (const float*)d_in[4];
    const float* b2  = (const float*)d_in[5];
    const float* eps = (const float*)d_in[6];
    float* out = (float*)d_out;

    detect_kernel<<<1, 128>>>(ei);
    init_h_kernel<<<(NN * D / 4 + 255) / 256, 256>>>(x, eps);
    scatter_kernel<<<(NE * 16 + 255) / 256, 256>>>(x, ei);

    const int SM1 = (8192 + 8192 + 128) * (int)sizeof(float);   // 66048 B
    const int SM2 = (8192 + 4096) * (int)sizeof(float);         // 49152 B
    cudaFuncSetAttribute(gemm1_kernel, cudaFuncAttributeMaxDynamicSharedMemorySize, SM1);
    cudaFuncSetAttribute(gemm2_kernel, cudaFuncAttributeMaxDynamicSharedMemorySize, SM2);

    const int NT = (NN + 127) / 128;   // 391 tiles
    gemm1_kernel<<<NT, 256, SM1>>>(W1, b1);
    gemm2_kernel<<<NT, 128, SM2>>>(W2, b2, out);
}

// round 4
// speedup vs baseline: 1.2992x; 1.1267x over previous
#include <cuda_runtime.h>

#define NN 50000
#define D  64
#define NE 800000
#define H  128
#define NT 782          // 64-row tiles
typedef unsigned long long ull;

// Scratch (static — no allocs allowed).
__device__ __align__(16) float g_h[NN * D];   // (1+eps)*x + scatter-sum
__device__ int g_idx_is64;

// ---- packed fp32x2 helpers (sm_100+ FFMA2; 2x fp32 throughput) -------------
__device__ __forceinline__ void ffma2(ull& d, ull a, ull b) {
    asm("fma.rn.f32x2 %0, %1, %2, %0;" : "+l"(d) : "l"(a), "l"(b));
}
__device__ __forceinline__ ull bcast2(float a) {
    ull r; asm("mov.b64 %0, {%1, %1};" : "=l"(r) : "f"(a)); return r;
}
__device__ __forceinline__ float2 unpk(ull v) {
    float2 r; asm("mov.b64 {%0, %1}, %2;" : "=f"(r.x), "=f"(r.y) : "l"(v)); return r;
}

// ---------------------------------------------------------------------------
// Kernel 1: g_h = (1+eps)*x.  Block 0 additionally detects the edge_index
// dtype: node ids are in [0,NN); if the buffer were int32, an int64 read
// packs two ids -> >= 2^32 unless the high word is 0 (P ~ (1/NN)^128).
// ---------------------------------------------------------------------------
__global__ void init_h_kernel(const float* __restrict__ x,
                              const float* __restrict__ eps,
                              const void* __restrict__ ei) {
    if (blockIdx.x == 0 && threadIdx.x < 128) {
        __shared__ int bad;
        if (threadIdx.x == 0) bad = 0;
        __syncwarp();
        __syncthreads();
        long long v = ((const long long*)ei)[threadIdx.x];
        if (v < 0 || v >= NN) atomicOr(&bad, 1);
        __syncthreads();
        if (threadIdx.x == 0) g_idx_is64 = !bad;
    }
    int i = blockIdx.x * blockDim.x + threadIdx.x;
    if (i < NN * D / 4) {
        float s = 1.0f + eps[0];
        float4 v = reinterpret_cast<const float4*>(x)[i];
        v.x *= s; v.y *= s; v.z *= s; v.w *= s;
        reinterpret_cast<float4*>(g_h)[i] = v;
    }
}

// ---------------------------------------------------------------------------
// Kernel 2: scatter-add, 16 threads/edge (contiguous 256B row),
// red.global.add.v4.f32. ~LTS floor.
// ---------------------------------------------------------------------------
__global__ void scatter_kernel(const float* __restrict__ x,
                               const void* __restrict__ ei) {
    int idx = blockIdx.x * blockDim.x + threadIdx.x;
    if (idx >= NE * 16) return;
    int e = idx >> 4;
    int c = idx & 15;
    int dst_n, src_n;
    if (g_idx_is64) {
        const long long* p = (const long long*)ei;
        dst_n = (int)p[e];
        src_n = (int)p[NE + e];
    } else {
        const int* p = (const int*)ei;
        dst_n = p[e];
        src_n = p[NE + e];
    }
    float4 v = reinterpret_cast<const float4*>(x + (size_t)src_n * D)[c];
    float* dst = g_h + (size_t)dst_n * D + c * 4;
    asm volatile("red.global.add.v4.f32 [%0], {%1, %2, %3, %4};"
                 :: "l"(dst), "f"(v.x), "f"(v.y), "f"(v.z), "f"(v.w)
                 : "memory");
}

// ---------------------------------------------------------------------------
// Kernel 3: fused MLP, persistent. Per 64-row tile:
//   phase 1: h1 = relu(h @ W1 + b1)   (64x128, FFMA2, acc in regs)
//   transpose h1 -> smem k-major (conflict-free STS.128)
//   phase 2: out = h1 @ W2 + b2       (64x64, FFMA2)
// 256 threads; W1/W2/biases staged once per block. smem 99KB -> 2 blocks/SM.
// ---------------------------------------------------------------------------
__global__ __launch_bounds__(256, 2)
void mlp_kernel(const float* __restrict__ W1, const float* __restrict__ b1,
                const float* __restrict__ W2, const float* __restrict__ b2,
                float* __restrict__ out) {
    extern __shared__ float sm[];
    float* sW1 = sm;            // 8192 floats [64][128] k-major
    float* sW2 = sm + 8192;     // 8192 floats [128][64] k-major
    float* sb1 = sm + 16384;    // 128
    float* sb2 = sm + 16512;    // 64
    float* uni = sm + 16576;    // 8192 floats: At=[64k][64r] (first 4096) / h1t=[128k][64r]
    int tid = threadIdx.x;
    int tx = tid & 15;          // rows 4tx..4tx+3
    int ty = tid >> 4;          // gemm1 cols 8ty..8ty+7; gemm2 cols 4ty..4ty+3

    for (int i = tid; i < 2048; i += 256)
        ((float4*)sW1)[i] = ((const float4*)W1)[i];
    for (int i = tid; i < 2048; i += 256)
        ((float4*)sW2)[i] = ((const float4*)W2)[i];
    if (tid < 128) sb1[tid] = b1[tid];
    if (tid < 64)  sb2[tid] = b2[tid];

    for (int tile = blockIdx.x; tile < NT; tile += gridDim.x) {
        int r0 = tile * 64;

        // ---- stage A tile k-major: At[k*64 + row] (conflict-free STS) ----
        for (int f = tid; f < 1024; f += 256) {
            int row = f & 63, c4 = f >> 6;
            int gr = r0 + row; if (gr >= NN) gr = NN - 1;
            float4 v = ((const float4*)g_h)[gr * 16 + c4];
            float* d = uni + (c4 * 4) * 64 + row;
            d[0] = v.x; d[64] = v.y; d[128] = v.z; d[192] = v.w;
        }
        __syncthreads();

        // ---- phase 1: 4 rows x 8 cols (4 f32x2 pairs) per thread ----
        ull acc1[4][4];
        {
            const ull* bp = (const ull*)(sb1 + 8 * ty);
            ull b0 = bp[0], b1p = bp[1], b2p = bp[2], b3p = bp[3];
#pragma unroll
            for (int i = 0; i < 4; i++) {
                acc1[i][0] = b0; acc1[i][1] = b1p; acc1[i][2] = b2p; acc1[i][3] = b3p;
            }
        }
#pragma unroll 8
        for (int k = 0; k < 64; k++) {
            float4 a = *(const float4*)(uni + k * 64 + 4 * tx);
            const ulonglong2* bp = (const ulonglong2*)(sW1 + k * H + 8 * ty);
            ulonglong2 bA = bp[0], bB = bp[1];
            ull pa[4] = { bcast2(a.x), bcast2(a.y), bcast2(a.z), bcast2(a.w) };
#pragma unroll
            for (int i = 0; i < 4; i++) {
                ffma2(acc1[i][0], pa[i], bA.x);
                ffma2(acc1[i][1], pa[i], bA.y);
                ffma2(acc1[i][2], pa[i], bB.x);
                ffma2(acc1[i][3], pa[i], bB.y);
            }
        }
        __syncthreads();   // all reads of At done before h1t overwrites it

        // ---- relu + transpose to h1t[k*64 + row], 4-row STS.128 ----
#pragma unroll
        for (int j = 0; j < 4; j++) {
            float2 v0 = unpk(acc1[0][j]), v1 = unpk(acc1[1][j]);
            float2 v2 = unpk(acc1[2][j]), v3 = unpk(acc1[3][j]);
            float4 lo = { fmaxf(v0.x,0.f), fmaxf(v1.x,0.f), fmaxf(v2.x,0.f), fmaxf(v3.x,0.f) };
            float4 hi = { fmaxf(v0.y,0.f), fmaxf(v1.y,0.f), fmaxf(v2.y,0.f), fmaxf(v3.y,0.f) };
            int c = 8 * ty + 2 * j;
            *(float4*)(uni + c * 64 + 4 * tx)       = lo;
            *(float4*)(uni + (c + 1) * 64 + 4 * tx) = hi;
        }
        __syncthreads();

        // ---- phase 2: 4 rows x 4 cols (2 pairs) per thread ----
        ull acc2[4][2];
        {
            const ull* bp = (const ull*)(sb2 + 4 * ty);
            ull b0 = bp[0], b1p = bp[1];
#pragma unroll
            for (int i = 0; i < 4; i++) { acc2[i][0] = b0; acc2[i][1] = b1p; }
        }
#pragma unroll 8
        for (int k = 0; k < H; k++) {
            float4 a = *(const float4*)(uni + k * 64 + 4 * tx);
            ulonglong2 bv = *(const ulonglong2*)(sW2 + k * 64 + 4 * ty);
            ull pa[4] = { bcast2(a.x), bcast2(a.y), bcast2(a.z), bcast2(a.w) };
#pragma unroll
            for (int i = 0; i < 4; i++) {
                ffma2(acc2[i][0], pa[i], bv.x);
                ffma2(acc2[i][1], pa[i], bv.y);
            }
        }

        // ---- store out tile ----
#pragma unroll
        for (int i = 0; i < 4; i++) {
            int r = r0 + 4 * tx + i;
            if (r < NN) {
                float2 lo = unpk(acc2[i][0]), hi = unpk(acc2[i][1]);
                float4 v = { lo.x, lo.y, hi.x, hi.y };
                ((float4*)(out + (size_t)r * D))[ty] = v;
            }
        }
        __syncthreads();   // h1t reads done before next tile's staging
    }
}

// ---------------------------------------------------------------------------
extern "C" void kernel_launch(void* const* d_in, const int* in_sizes, int n_in,
                              void* d_out, int out_size) {
    const float* x   = (const float*)d_in[0];
    const void*  ei  = d_in[1];
    const float* W1  = (const float*)d_in[2];
    const float* b1  = (const float*)d_in[3];
    const float* W2  = (const float*)d_in[4];
    const float* b2  = (const float*)d_in[5];
    const float* eps = (const float*)d_in[6];
    float* out = (float*)d_out;

    init_h_kernel<<<(NN * D / 4 + 255) / 256, 256>>>(x, eps, ei);
    scatter_kernel<<<(NE * 16 + 255) / 256, 256>>>(x, ei);

    const int SMEM = (8192 + 8192 + 128 + 64 + 8192) * (int)sizeof(float); // 99072 B
    cudaFuncSetAttribute(mlp_kernel, cudaFuncAttributeMaxDynamicSharedMemorySize, SMEM);
    mlp_kernel<<<296, 256, SMEM>>>(W1, b1, W2, b2, out);
}